// round 10
// baseline (speedup 1.0000x reference)
#include <cuda_runtime.h>
#include <cuda_fp16.h>
#include <cstdint>
#include <cstddef>

// ---------------------------------------------------------------------------
// Problem dims
// ---------------------------------------------------------------------------
#define B_    4096
#define DIN   32000
#define H0R   4000
#define H1R   4000
#define TLR   2000
#define H0P   4096      // padded
#define H1P   4096
#define TLP   2048

// ---------------------------------------------------------------------------
// Scratch (device globals -- allocation-free per harness rules)
// ---------------------------------------------------------------------------
__device__ __align__(1024) __half g_Xh  [(size_t)B_  * DIN];   // X fp16 [4096, 32000]
__device__ __align__(1024) __half g_WinT[(size_t)H0P * DIN];   // W_in^T fp16 [4096, 32000]
__device__ __align__(1024) __half g_A0  [(size_t)B_  * H0P];   // layer0 out fp16
__device__ __align__(1024) __half g_W1T [(size_t)H1P * H0P];   // W1^T fp16
__device__ __align__(1024) __half g_A1  [(size_t)B_  * H1P];   // layer1 out fp16
__device__ __align__(1024) __half g_W2T [(size_t)TLP * H1P];   // W2^T fp16

// ---------------------------------------------------------------------------
// GEMM config: 256x128x32 tiles, 4-stage cp.async pipeline, 8 warps (4x2),
// each warp computes 64x64 with m16n8k16 HMMA (fp16 in, fp32 accum).
// ---------------------------------------------------------------------------
static constexpr int BM = 256, BN = 128, BK = 32, STAGES = 4;
static constexpr int RSH    = 40;               // halves per smem row (80 B, padded)
static constexpr int A_ST_H = BM * RSH;         // 10240 halves per A stage
static constexpr int B_ST_H = BN * RSH;         // 5120
static constexpr int STG_H  = A_ST_H + B_ST_H;  // 15360 halves = 30720 B
static constexpr int SMEM_BYTES = STAGES * STG_H * 2;  // 122880 B

__device__ __forceinline__ void cp16(uint32_t saddr, const void* g) {
    asm volatile("cp.async.cg.shared.global [%0], [%1], 16;\n" :: "r"(saddr), "l"(g));
}
__device__ __forceinline__ void cp_commit() {
    asm volatile("cp.async.commit_group;\n" ::: "memory");
}
template <int N> __device__ __forceinline__ void cp_wait() {
    asm volatile("cp.async.wait_group %0;\n" :: "n"(N) : "memory");
}
__device__ __forceinline__ void ldsm_x4(uint32_t& r0, uint32_t& r1, uint32_t& r2, uint32_t& r3,
                                        uint32_t a) {
    asm volatile("ldmatrix.sync.aligned.m8n8.x4.shared.b16 {%0,%1,%2,%3}, [%4];\n"
                 : "=r"(r0), "=r"(r1), "=r"(r2), "=r"(r3) : "r"(a));
}
__device__ __forceinline__ void mma16816(float* d, const uint32_t* a, const uint32_t* b) {
    asm volatile(
        "mma.sync.aligned.m16n8k16.row.col.f32.f16.f16.f32 "
        "{%0,%1,%2,%3}, {%4,%5,%6,%7}, {%8,%9}, {%0,%1,%2,%3};\n"
        : "+f"(d[0]), "+f"(d[1]), "+f"(d[2]), "+f"(d[3])
        : "r"(a[0]), "r"(a[1]), "r"(a[2]), "r"(a[3]), "r"(b[0]), "r"(b[1]));
}

// D[M,N] = A[M,K] @ Bw^T where A is [M rows, K cols] fp16 row-major,
// Bw is [N rows, K cols] fp16 row-major (pre-transposed weights).
template <bool OUT_F32>
__global__ void __launch_bounds__(256, 1)
mlp_gemm(const __half* __restrict__ A, const __half* __restrict__ Bw,
         const float* __restrict__ bias, void* __restrict__ outp,
         int lda, int ldb, int ktiles, int ntiles_g,
         int n_real, int out_stride, int relu)
{
    extern __shared__ __half sh[];
    uint32_t sb = (uint32_t)__cvta_generic_to_shared(sh);

    // grid swizzle: groups of 8 mtiles so a wave shares an L2 K-window
    const int GM = 8;
    int per_group = GM * ntiles_g;
    int grp = blockIdx.x / per_group;
    int rem = blockIdx.x % per_group;
    int mtile = grp * GM + (rem % GM);
    int ntile = rem / GM;

    int tid = threadIdx.x;
    int lane = tid & 31;
    int wid  = tid >> 5;
    int warp_m = wid & 3;    // 0..3 -> 64-row block
    int warp_n = wid >> 2;   // 0..1 -> 64-col block

    // ---- per-thread cp.async source pointers (advance by BK per stage) ----
    int row0 = tid >> 2;                 // 0..63
    int c4   = (tid & 3) * 8;            // half offset within row (0,8,16,24)
    const __half* gA[4];
    uint32_t dA[4];
    #pragma unroll
    for (int r = 0; r < 4; r++) {
        gA[r] = A + ((long)mtile * BM + row0 + 64 * r) * (long)lda + c4;
        dA[r] = (uint32_t)(((row0 + 64 * r) * RSH + c4) * 2);
    }
    const __half* gB[2];
    uint32_t dB[2];
    #pragma unroll
    for (int r = 0; r < 2; r++) {
        gB[r] = Bw + ((long)ntile * BN + row0 + 64 * r) * (long)ldb + c4;
        dB[r] = (uint32_t)(A_ST_H * 2) + (uint32_t)(((row0 + 64 * r) * RSH + c4) * 2);
    }

    auto load_stage = [&](int s) {
        uint32_t stg = sb + (uint32_t)(s * STG_H * 2);
        #pragma unroll
        for (int r = 0; r < 4; r++) { cp16(stg + dA[r], gA[r]); gA[r] += BK; }
        #pragma unroll
        for (int r = 0; r < 2; r++) { cp16(stg + dB[r], gB[r]); gB[r] += BK; }
    };

    float acc[4][8][4];
    #pragma unroll
    for (int i = 0; i < 4; i++)
        #pragma unroll
        for (int j = 0; j < 8; j++)
            #pragma unroll
            for (int k = 0; k < 4; k++) acc[i][j][k] = 0.0f;

    // ---- ldmatrix address precompute (lane-dependent, stage-relative) ----
    // A frags: 16x16 tiles at rows warp_m*64 + mt*16
    uint32_t a_off[4];
    {
        int r  = warp_m * 64 + (lane & 15);
        int kh = (lane >> 4) * 8;
        #pragma unroll
        for (int mt = 0; mt < 4; mt++)
            a_off[mt] = (uint32_t)(((r + mt * 16) * RSH + kh) * 2);
    }
    // B frags: 16(n)x16(k) blocks at n = warp_n*64 + nb*16
    uint32_t b_off[4];
    {
        int t  = lane >> 3;
        int n  = warp_n * 64 + (t >> 1) * 8 + (lane & 7);
        int kh = (t & 1) * 8;
        #pragma unroll
        for (int nb = 0; nb < 4; nb++)
            b_off[nb] = (uint32_t)(A_ST_H * 2) + (uint32_t)(((n + nb * 16) * RSH + kh) * 2);
    }

    // ---- prologue: fill STAGES-1 stages ----
    #pragma unroll
    for (int s = 0; s < STAGES - 1; s++) { load_stage(s); cp_commit(); }

    // ---- mainloop ----
    for (int i = 0; i < ktiles; i++) {
        cp_wait<STAGES - 2>();
        __syncthreads();

        if (i + STAGES - 1 < ktiles) load_stage((i + STAGES - 1) & (STAGES - 1));
        cp_commit();

        uint32_t stg = sb + (uint32_t)((i & (STAGES - 1)) * STG_H * 2);
        #pragma unroll
        for (int ks = 0; ks < 2; ks++) {
            uint32_t khoff = (uint32_t)(ks * 16 * 2);
            uint32_t ar[4][4];
            #pragma unroll
            for (int mt = 0; mt < 4; mt++)
                ldsm_x4(ar[mt][0], ar[mt][1], ar[mt][2], ar[mt][3],
                        stg + a_off[mt] + khoff);
            uint32_t br[4][4];
            #pragma unroll
            for (int nb = 0; nb < 4; nb++)
                ldsm_x4(br[nb][0], br[nb][1], br[nb][2], br[nb][3],
                        stg + b_off[nb] + khoff);
            #pragma unroll
            for (int mt = 0; mt < 4; mt++)
                #pragma unroll
                for (int nt = 0; nt < 8; nt++)
                    mma16816(acc[mt][nt], ar[mt], &br[nt >> 1][(nt & 1) * 2]);
        }
    }

    // ---- epilogue: bias (+ReLU) fused, straight from registers ----
    int mbase = mtile * BM + warp_m * 64;
    int nbase = ntile * BN + warp_n * 64;
    #pragma unroll
    for (int mt = 0; mt < 4; mt++) {
        long r0 = mbase + mt * 16 + (lane >> 2);
        #pragma unroll
        for (int nt = 0; nt < 8; nt++) {
            int col = nbase + nt * 8 + (lane & 3) * 2;
            if (col < n_real) {
                float2 bb = *(const float2*)(bias + col);
                float v0 = acc[mt][nt][0] + bb.x;
                float v1 = acc[mt][nt][1] + bb.y;
                float v2 = acc[mt][nt][2] + bb.x;
                float v3 = acc[mt][nt][3] + bb.y;
                if (relu) {
                    v0 = fmaxf(v0, 0.0f); v1 = fmaxf(v1, 0.0f);
                    v2 = fmaxf(v2, 0.0f); v3 = fmaxf(v3, 0.0f);
                }
                if (OUT_F32) {
                    float* o = (float*)outp;
                    *(float2*)(o + r0 * out_stride + col)       = make_float2(v0, v1);
                    *(float2*)(o + (r0 + 8) * out_stride + col) = make_float2(v2, v3);
                } else {
                    __half* o = (__half*)outp;
                    *(__half2*)(o + r0 * out_stride + col)       = __floats2half2_rn(v0, v1);
                    *(__half2*)(o + (r0 + 8) * out_stride + col) = __floats2half2_rn(v2, v3);
                }
            }
        }
    }
}

// ---------------------------------------------------------------------------
// fp32 -> fp16 straight conversion (X)
// ---------------------------------------------------------------------------
__global__ void scb_f2h_kernel(const float* __restrict__ in, __half* __restrict__ out, size_t n4) {
    size_t i = (size_t)blockIdx.x * blockDim.x + threadIdx.x;
    size_t stride = (size_t)gridDim.x * blockDim.x;
    for (; i < n4; i += stride) {
        float4 v = ((const float4*)in)[i];
        __half2* o = (__half2*)out + 2 * i;
        o[0] = __floats2half2_rn(v.x, v.y);
        o[1] = __floats2half2_rn(v.z, v.w);
    }
}

// ---------------------------------------------------------------------------
// fp32 [K,N] -> fp16 transposed+padded [Np, Kp] (zero pad)
// ---------------------------------------------------------------------------
__global__ void scb_transpose_f2h(const float* __restrict__ in, __half* __restrict__ out,
                                  int K, int N, int Kp) {
    __shared__ float tile[32][33];
    int k0 = blockIdx.x * 32, n0 = blockIdx.y * 32;
    int tx = threadIdx.x, ty = threadIdx.y;  // 32 x 8
    #pragma unroll
    for (int j = 0; j < 32; j += 8) {
        int k = k0 + ty + j, n = n0 + tx;
        tile[ty + j][tx] = (k < K && n < N) ? in[(long)k * N + n] : 0.0f;
    }
    __syncthreads();
    #pragma unroll
    for (int j = 0; j < 32; j += 8) {
        int n = n0 + ty + j, k = k0 + tx;
        out[(long)n * Kp + k] = __float2half_rn(tile[tx][ty + j]);
    }
}

// ---------------------------------------------------------------------------
// kernel_launch
// ---------------------------------------------------------------------------
extern "C" void kernel_launch(void* const* d_in, const int* in_sizes, int n_in,
                              void* d_out, int out_size) {
    const float* X    = (const float*)d_in[0];
    const float* Win  = (const float*)d_in[1];
    const float* b_in = (const float*)d_in[2];
    const float* W1   = (const float*)d_in[3];
    const float* b1   = (const float*)d_in[4];
    const float* W2   = (const float*)d_in[5];
    const float* b2   = (const float*)d_in[6];

    __half *Xh, *WinT, *A0, *W1T, *A1, *W2T;
    cudaGetSymbolAddress((void**)&Xh,   g_Xh);
    cudaGetSymbolAddress((void**)&WinT, g_WinT);
    cudaGetSymbolAddress((void**)&A0,   g_A0);
    cudaGetSymbolAddress((void**)&W1T,  g_W1T);
    cudaGetSymbolAddress((void**)&A1,   g_A1);
    cudaGetSymbolAddress((void**)&W2T,  g_W2T);

    cudaFuncSetAttribute(mlp_gemm<false>,
                         cudaFuncAttributeMaxDynamicSharedMemorySize, SMEM_BYTES);
    cudaFuncSetAttribute(mlp_gemm<true>,
                         cudaFuncAttributeMaxDynamicSharedMemorySize, SMEM_BYTES);

    // --- conversions / weight transposes (deterministic, every call) ---
    scb_f2h_kernel<<<4096, 256>>>(X, Xh, ((size_t)B_ * DIN) / 4);
    scb_transpose_f2h<<<dim3(DIN / 32, H0P / 32), dim3(32, 8)>>>(Win, WinT, DIN, H0R, DIN);
    scb_transpose_f2h<<<dim3(H0P / 32, H1P / 32), dim3(32, 8)>>>(W1,  W1T,  H0R, H1R, H0P);
    scb_transpose_f2h<<<dim3(H1P / 32, TLP / 32), dim3(32, 8)>>>(W2,  W2T,  H1R, TLR, H1P);

    int mt = B_ / BM;           // 16
    int nt0 = H0P / BN;         // 32 n-tiles (covers 4000 w/ mask)
    int nt1 = H1P / BN;         // 32
    int nt2 = TLP / BN;         // 16 (covers 2000 w/ mask)

    // --- layer 0: A0 = X @ W_in + b_in (no relu), fp16 out [4096, 4096p] ---
    mlp_gemm<false><<<mt * nt0, 256, SMEM_BYTES>>>(
        Xh, WinT, b_in, A0, DIN, DIN, DIN / BK, nt0, H0R, H0P, 0);

    // --- layer 1: A1 = relu(A0 @ W1 + b1), fp16 out; K=4000 (real) ---
    mlp_gemm<false><<<mt * nt1, 256, SMEM_BYTES>>>(
        A0, W1T, b1, A1, H0P, H0P, H0R / BK, nt1, H1R, H1P, 1);

    // --- layer 2: out = relu(A1 @ W2 + b2), fp32 out [4096, 2000]; K=4000 ---
    mlp_gemm<true><<<mt * nt2, 256, SMEM_BYTES>>>(
        A1, W2T, b2, d_out, H1P, H1P, H1R / BK, nt2, TLR, TLR, 1);
}

// round 11
// speedup vs baseline: 1.2660x; 1.2660x over previous
#include <cuda_runtime.h>
#include <cuda_fp16.h>
#include <cstdint>
#include <cstddef>

// ---------------------------------------------------------------------------
// Problem dims
// ---------------------------------------------------------------------------
#define B_    4096
#define DIN   32000
#define H0R   4000
#define H1R   4000
#define TLR   2000
#define H0P   4096      // padded
#define H1P   4096
#define TLP   2048

// ---------------------------------------------------------------------------
// Scratch (device globals -- allocation-free per harness rules)
// ---------------------------------------------------------------------------
__device__ __align__(1024) __half g_Xh  [(size_t)B_  * DIN];   // X fp16 [4096, 32000]
__device__ __align__(1024) __half g_WinT[(size_t)H0P * DIN];   // W_in^T fp16 [4096, 32000]
__device__ __align__(1024) __half g_A0  [(size_t)B_  * H0P];   // layer0 out fp16
__device__ __align__(1024) __half g_W1T [(size_t)H1P * H0P];   // W1^T fp16
__device__ __align__(1024) __half g_A1  [(size_t)B_  * H1P];   // layer1 out fp16
__device__ __align__(1024) __half g_W2T [(size_t)TLP * H1P];   // W2^T fp16

// ---------------------------------------------------------------------------
// GEMM config: 128x128x32 tiles, 4-stage cp.async pipeline, 8 warps (2x4),
// each warp computes 64x32 with m16n8k16 HMMA (fp16 in, fp32 accum).
// 2 CTAs per SM (160KB smem, 128 regs/thread) for latency hiding.
// ---------------------------------------------------------------------------
static constexpr int BM = 128, BN = 128, BK = 32, STAGES = 4;
static constexpr int RSH    = 40;               // halves per smem row (80 B, padded)
static constexpr int A_ST_H = BM * RSH;         // 5120 halves per A stage
static constexpr int B_ST_H = BN * RSH;
static constexpr int STG_H  = A_ST_H + B_ST_H;  // 10240 halves = 20480 B
static constexpr int SMEM_BYTES = STAGES * STG_H * 2;  // 81920 B

__device__ __forceinline__ void cp16(uint32_t saddr, const void* g) {
    asm volatile("cp.async.cg.shared.global [%0], [%1], 16;\n" :: "r"(saddr), "l"(g));
}
__device__ __forceinline__ void cp_commit() {
    asm volatile("cp.async.commit_group;\n" ::: "memory");
}
template <int N> __device__ __forceinline__ void cp_wait() {
    asm volatile("cp.async.wait_group %0;\n" :: "n"(N) : "memory");
}
__device__ __forceinline__ void ldsm_x4(uint32_t& r0, uint32_t& r1, uint32_t& r2, uint32_t& r3,
                                        uint32_t a) {
    asm volatile("ldmatrix.sync.aligned.m8n8.x4.shared.b16 {%0,%1,%2,%3}, [%4];\n"
                 : "=r"(r0), "=r"(r1), "=r"(r2), "=r"(r3) : "r"(a));
}
__device__ __forceinline__ void mma16816(float* d, const uint32_t* a, const uint32_t* b) {
    asm volatile(
        "mma.sync.aligned.m16n8k16.row.col.f32.f16.f16.f32 "
        "{%0,%1,%2,%3}, {%4,%5,%6,%7}, {%8,%9}, {%0,%1,%2,%3};\n"
        : "+f"(d[0]), "+f"(d[1]), "+f"(d[2]), "+f"(d[3])
        : "r"(a[0]), "r"(a[1]), "r"(a[2]), "r"(a[3]), "r"(b[0]), "r"(b[1]));
}

// D[M,N] = A[M,K] @ Bw^T where A is [M rows, K cols] fp16 row-major,
// Bw is [N rows, K cols] fp16 row-major (pre-transposed weights).
template <bool OUT_F32>
__global__ void __launch_bounds__(256, 2)
mlp_gemm(const __half* __restrict__ A, const __half* __restrict__ Bw,
         const float* __restrict__ bias, void* __restrict__ outp,
         int lda, int ldb, int ktiles, int ntiles_g,
         int n_real, int out_stride, int relu)
{
    extern __shared__ __half sh[];
    uint32_t sb = (uint32_t)__cvta_generic_to_shared(sh);

    // grid swizzle: groups of 8 mtiles so a wave shares an L2 K-window
    const int GM = 8;
    int per_group = GM * ntiles_g;
    int grp = blockIdx.x / per_group;
    int rem = blockIdx.x % per_group;
    int mtile = grp * GM + (rem % GM);
    int ntile = rem / GM;

    int tid = threadIdx.x;
    int lane = tid & 31;
    int wid  = tid >> 5;
    int warp_m = wid >> 2;   // 0..1 -> 64-row block
    int warp_n = wid & 3;    // 0..3 -> 32-col block

    // ---- per-thread cp.async source pointers (advance by BK per stage) ----
    int row0 = tid >> 2;                 // 0..63
    int c4   = (tid & 3) * 8;            // half offset within row (0,8,16,24)
    const __half* gA0 = A  + ((long)mtile * BM + row0)      * (long)lda + c4;
    const __half* gA1 = A  + ((long)mtile * BM + row0 + 64) * (long)lda + c4;
    const __half* gB0 = Bw + ((long)ntile * BN + row0)      * (long)ldb + c4;
    const __half* gB1 = Bw + ((long)ntile * BN + row0 + 64) * (long)ldb + c4;
    uint32_t dA0 = (uint32_t)((row0 * RSH + c4) * 2);
    uint32_t dA1 = (uint32_t)(((row0 + 64) * RSH + c4) * 2);
    uint32_t dB0 = (uint32_t)(A_ST_H * 2) + dA0;
    uint32_t dB1 = (uint32_t)(A_ST_H * 2) + dA1;

    auto load_stage = [&](int s) {
        uint32_t stg = sb + (uint32_t)(s * STG_H * 2);
        cp16(stg + dA0, gA0);
        cp16(stg + dA1, gA1);
        cp16(stg + dB0, gB0);
        cp16(stg + dB1, gB1);
        gA0 += BK; gA1 += BK; gB0 += BK; gB1 += BK;
    };

    float acc[4][4][4];
    #pragma unroll
    for (int i = 0; i < 4; i++)
        #pragma unroll
        for (int j = 0; j < 4; j++)
            #pragma unroll
            for (int k = 0; k < 4; k++) acc[i][j][k] = 0.0f;

    // ---- ldmatrix address precompute (lane-dependent, stage-relative) ----
    uint32_t a_off[4];
    {
        int r  = warp_m * 64 + (lane & 15);
        int kh = (lane >> 4) * 8;
        #pragma unroll
        for (int mt = 0; mt < 4; mt++)
            a_off[mt] = (uint32_t)(((r + mt * 16) * RSH + kh) * 2);
    }
    uint32_t b_off[2];
    {
        int t  = lane >> 3;
        int n  = warp_n * 32 + (t >> 1) * 8 + (lane & 7);
        int kh = (t & 1) * 8;
        #pragma unroll
        for (int nb = 0; nb < 2; nb++)
            b_off[nb] = (uint32_t)(A_ST_H * 2) + (uint32_t)(((n + nb * 16) * RSH + kh) * 2);
    }

    // ---- prologue: fill STAGES-1 stages ----
    #pragma unroll
    for (int s = 0; s < STAGES - 1; s++) { load_stage(s); cp_commit(); }

    // ---- mainloop ----
    for (int i = 0; i < ktiles; i++) {
        cp_wait<STAGES - 2>();
        __syncthreads();

        if (i + STAGES - 1 < ktiles) load_stage((i + STAGES - 1) & (STAGES - 1));
        cp_commit();

        uint32_t stg = sb + (uint32_t)((i & (STAGES - 1)) * STG_H * 2);
        #pragma unroll
        for (int ks = 0; ks < 2; ks++) {
            uint32_t khoff = (uint32_t)(ks * 16 * 2);
            uint32_t ar[4][4];
            #pragma unroll
            for (int mt = 0; mt < 4; mt++)
                ldsm_x4(ar[mt][0], ar[mt][1], ar[mt][2], ar[mt][3],
                        stg + a_off[mt] + khoff);
            uint32_t br[2][4];
            #pragma unroll
            for (int nb = 0; nb < 2; nb++)
                ldsm_x4(br[nb][0], br[nb][1], br[nb][2], br[nb][3],
                        stg + b_off[nb] + khoff);
            #pragma unroll
            for (int mt = 0; mt < 4; mt++)
                #pragma unroll
                for (int nt = 0; nt < 4; nt++)
                    mma16816(acc[mt][nt], ar[mt], &br[nt >> 1][(nt & 1) * 2]);
        }
    }

    // ---- epilogue: bias (+ReLU) fused, straight from registers ----
    int mbase = mtile * BM + warp_m * 64;
    int nbase = ntile * BN + warp_n * 32;
    #pragma unroll
    for (int mt = 0; mt < 4; mt++) {
        long r0 = mbase + mt * 16 + (lane >> 2);
        #pragma unroll
        for (int nt = 0; nt < 4; nt++) {
            int col = nbase + nt * 8 + (lane & 3) * 2;
            if (col < n_real) {
                float2 bb = *(const float2*)(bias + col);
                float v0 = acc[mt][nt][0] + bb.x;
                float v1 = acc[mt][nt][1] + bb.y;
                float v2 = acc[mt][nt][2] + bb.x;
                float v3 = acc[mt][nt][3] + bb.y;
                if (relu) {
                    v0 = fmaxf(v0, 0.0f); v1 = fmaxf(v1, 0.0f);
                    v2 = fmaxf(v2, 0.0f); v3 = fmaxf(v3, 0.0f);
                }
                if (OUT_F32) {
                    float* o = (float*)outp;
                    *(float2*)(o + r0 * out_stride + col)       = make_float2(v0, v1);
                    *(float2*)(o + (r0 + 8) * out_stride + col) = make_float2(v2, v3);
                } else {
                    __half* o = (__half*)outp;
                    *(__half2*)(o + r0 * out_stride + col)       = __floats2half2_rn(v0, v1);
                    *(__half2*)(o + (r0 + 8) * out_stride + col) = __floats2half2_rn(v2, v3);
                }
            }
        }
    }
}

// ---------------------------------------------------------------------------
// fp32 -> fp16 straight conversion (X)
// ---------------------------------------------------------------------------
__global__ void scb_f2h_kernel(const float* __restrict__ in, __half* __restrict__ out, size_t n4) {
    size_t i = (size_t)blockIdx.x * blockDim.x + threadIdx.x;
    size_t stride = (size_t)gridDim.x * blockDim.x;
    for (; i < n4; i += stride) {
        float4 v = ((const float4*)in)[i];
        __half2* o = (__half2*)out + 2 * i;
        o[0] = __floats2half2_rn(v.x, v.y);
        o[1] = __floats2half2_rn(v.z, v.w);
    }
}

// ---------------------------------------------------------------------------
// fp32 [K,N] -> fp16 transposed+padded [Np, Kp] (zero pad)
// ---------------------------------------------------------------------------
__global__ void scb_transpose_f2h(const float* __restrict__ in, __half* __restrict__ out,
                                  int K, int N, int Kp) {
    __shared__ float tile[32][33];
    int k0 = blockIdx.x * 32, n0 = blockIdx.y * 32;
    int tx = threadIdx.x, ty = threadIdx.y;  // 32 x 8
    #pragma unroll
    for (int j = 0; j < 32; j += 8) {
        int k = k0 + ty + j, n = n0 + tx;
        tile[ty + j][tx] = (k < K && n < N) ? in[(long)k * N + n] : 0.0f;
    }
    __syncthreads();
    #pragma unroll
    for (int j = 0; j < 32; j += 8) {
        int n = n0 + ty + j, k = k0 + tx;
        out[(long)n * Kp + k] = __float2half_rn(tile[tx][ty + j]);
    }
}

// ---------------------------------------------------------------------------
// kernel_launch
// ---------------------------------------------------------------------------
extern "C" void kernel_launch(void* const* d_in, const int* in_sizes, int n_in,
                              void* d_out, int out_size) {
    const float* X    = (const float*)d_in[0];
    const float* Win  = (const float*)d_in[1];
    const float* b_in = (const float*)d_in[2];
    const float* W1   = (const float*)d_in[3];
    const float* b1   = (const float*)d_in[4];
    const float* W2   = (const float*)d_in[5];
    const float* b2   = (const float*)d_in[6];

    __half *Xh, *WinT, *A0, *W1T, *A1, *W2T;
    cudaGetSymbolAddress((void**)&Xh,   g_Xh);
    cudaGetSymbolAddress((void**)&WinT, g_WinT);
    cudaGetSymbolAddress((void**)&A0,   g_A0);
    cudaGetSymbolAddress((void**)&W1T,  g_W1T);
    cudaGetSymbolAddress((void**)&A1,   g_A1);
    cudaGetSymbolAddress((void**)&W2T,  g_W2T);

    cudaFuncSetAttribute(mlp_gemm<false>,
                         cudaFuncAttributeMaxDynamicSharedMemorySize, SMEM_BYTES);
    cudaFuncSetAttribute(mlp_gemm<true>,
                         cudaFuncAttributeMaxDynamicSharedMemorySize, SMEM_BYTES);

    // --- conversions / weight transposes (deterministic, every call) ---
    scb_f2h_kernel<<<4096, 256>>>(X, Xh, ((size_t)B_ * DIN) / 4);
    scb_transpose_f2h<<<dim3(DIN / 32, H0P / 32), dim3(32, 8)>>>(Win, WinT, DIN, H0R, DIN);
    scb_transpose_f2h<<<dim3(H0P / 32, H1P / 32), dim3(32, 8)>>>(W1,  W1T,  H0R, H1R, H0P);
    scb_transpose_f2h<<<dim3(H1P / 32, TLP / 32), dim3(32, 8)>>>(W2,  W2T,  H1R, TLR, H1P);

    int mt = B_ / BM;           // 32
    int nt0 = H0P / BN;         // 32 (covers 4000 w/ mask)
    int nt1 = H1P / BN;         // 32
    int nt2 = TLP / BN;         // 16 (covers 2000 w/ mask)

    // --- layer 0: A0 = X @ W_in + b_in (no relu), fp16 out [4096, 4096p] ---
    mlp_gemm<false><<<mt * nt0, 256, SMEM_BYTES>>>(
        Xh, WinT, b_in, A0, DIN, DIN, DIN / BK, nt0, H0R, H0P, 0);

    // --- layer 1: A1 = relu(A0 @ W1 + b1), fp16 out; K=4000 (real) ---
    mlp_gemm<false><<<mt * nt1, 256, SMEM_BYTES>>>(
        A0, W1T, b1, A1, H0P, H0P, H0R / BK, nt1, H1R, H1P, 1);

    // --- layer 2: out = relu(A1 @ W2 + b2), fp32 out [4096, 2000]; K=4000 ---
    mlp_gemm<true><<<mt * nt2, 256, SMEM_BYTES>>>(
        A1, W2T, b2, d_out, H1P, H1P, H1R / BK, nt2, TLR, TLR, 1);
}